// round 12
// baseline (speedup 1.0000x reference)
#include <cuda_runtime.h>
#include <cuda_fp16.h>
#include <cstdint>

#define NIMG 4
#define CIN  256
#define HW   16384
#define MLP  128
#define NATT 16
#define NBIN 64
#define BP   64      // pixels per block (MLP kernel)

#define SX   72      // halves stride, x tile [CIN][BP]    (36 words % 32 == 4 -> conflict-free)
#define SW1  264     // halves stride, w1 [MLP][CIN]
#define SW2  136     // halves stride, w2 [NATT][MLP]
#define SH   72      // halves stride, H tile (aliases x region)
#define SAS  68      // floats stride, A tile (aliases w1 region)

#define OFF_X   0
#define OFF_W1  (CIN * SX * 2)               // 36864
#define OFF_W2  (OFF_W1 + MLP * SW1 * 2)     // 104448
#define SMEM_TOTAL (OFF_W2 + NATT * SW2 * 2) // 108800 -> 2 CTAs/SM

// C = sqrt(300 * log2(e)); exp(-300 dx^2) = 2^(-(C*dx)^2)
#define CSCALE 20.80405045f
#define INVC   0.048067556f

// device-global scratch (no runtime allocation allowed)
__device__ __half g_w1h[MLP * CIN];
__device__ __half g_w2h[NATT * MLP];
__device__ float  g_A[NIMG * NATT * HW];    // 4 MB, C-scaled A

#define NW1   (MLP * CIN / 2)               // 16384 half2
#define NW2   (NATT * MLP / 2)              // 1024 half2

// ---------------- kernel 0: weight fp32 -> fp16 (tiny) ----------------
__global__ void __launch_bounds__(256)
convert_weights(const float* __restrict__ w1, const float* __restrict__ w2) {
    int j = blockIdx.x * blockDim.x + threadIdx.x;
    if (j < NW1) {
        float2 v = __ldg((const float2*)w1 + j);
        *(half2*)&g_w1h[2 * j] = __floats2half2_rn(v.x, v.y);
    } else if (j < NW1 + NW2) {
        int k = j - NW1;
        float2 v = __ldg((const float2*)w2 + k);
        *(half2*)&g_w2h[2 * k] = __floats2half2_rn(v.x, v.y);
    }
}

__device__ __forceinline__ uint32_t smem_u32(const void* p) {
    return (uint32_t)__cvta_generic_to_shared(p);
}
__device__ __forceinline__ void cpa16(uint32_t dst, const void* src) {
    asm volatile("cp.async.ca.shared.global [%0], [%1], 16;" :: "r"(dst), "l"(src));
}
__device__ __forceinline__ void ldsm4(uint32_t* r, uint32_t a) {
    asm volatile("ldmatrix.sync.aligned.m8n8.x4.shared.b16 {%0,%1,%2,%3}, [%4];"
                 : "=r"(r[0]), "=r"(r[1]), "=r"(r[2]), "=r"(r[3]) : "r"(a));
}
__device__ __forceinline__ void ldsm4t(uint32_t& r0, uint32_t& r1, uint32_t& r2, uint32_t& r3, uint32_t a) {
    asm volatile("ldmatrix.sync.aligned.m8n8.x4.trans.shared.b16 {%0,%1,%2,%3}, [%4];"
                 : "=r"(r0), "=r"(r1), "=r"(r2), "=r"(r3) : "r"(a));
}
__device__ __forceinline__ void mma16816(float* c, const uint32_t* a, uint32_t b0, uint32_t b1) {
    asm volatile("mma.sync.aligned.m16n8k16.row.col.f32.f16.f16.f32 "
                 "{%0,%1,%2,%3}, {%4,%5,%6,%7}, {%8,%9}, {%0,%1,%2,%3};"
                 : "+f"(c[0]), "+f"(c[1]), "+f"(c[2]), "+f"(c[3])
                 : "r"(a[0]), "r"(a[1]), "r"(a[2]), "r"(a[3]), "r"(b0), "r"(b1));
}
__device__ __forceinline__ float softplus_f(float v) {
    return fmaxf(v, 0.0f) + log1pf(__expf(-fabsf(v)));
}

// ---------------- kernel 1: fused 1x1-conv MLP head -> scaled A scratch ----------------
// BP=64 px/CTA, 108.8KB smem -> 2 CTAs/SM; x converted fp32->fp16 inline.
__global__ void __launch_bounds__(256, 2)
zoe_mlp_kernel(const float* __restrict__ xg,
               const float* __restrict__ b1,
               const float* __restrict__ b2) {
    extern __shared__ char smem[];
    __half* sx  = (__half*)(smem + OFF_X);
    __half* sw1 = (__half*)(smem + OFF_W1);
    __half* sw2 = (__half*)(smem + OFF_W2);
    __half* sH  = sx;                       // H tile [128][SH] aliases x region
    float*  sA  = (float*)(smem + OFF_W1);  // A tile [16][SAS] aliases w1 region

    const int tid = threadIdx.x;
    const int blk = blockIdx.x;             // 0..1023
    const int n   = blk >> 8;               // image
    const int p0  = (blk & 255) * BP;       // pixel tile start

    // ---- issue weight cp.async first (fire-and-forget) ----
    {
        const uint32_t sw1b = smem_u32(sw1);
        #pragma unroll 4
        for (int i = tid; i < MLP * 32; i += 256) {       // 256 halves/row = 32 chunks
            int m = i >> 5, ch = i & 31;
            cpa16(sw1b + (uint32_t)(m * (SW1 * 2) + ch * 16), g_w1h + m * CIN + ch * 8);
        }
        const uint32_t sw2b = smem_u32(sw2);
        for (int i = tid; i < NATT * 16; i += 256) {      // 128 halves/row = 16 chunks
            int m = i >> 4, ch = i & 15;
            cpa16(sw2b + (uint32_t)(m * (SW2 * 2) + ch * 16), g_w2h + m * MLP + ch * 8);
        }
        asm volatile("cp.async.commit_group;");
    }
    // ---- stage x tile fp32 -> fp16 inline (overlaps the weight copy) ----
    {
        const float* xb = xg + (size_t)n * CIN * HW + p0;
        #pragma unroll 8
        for (int i = tid; i < CIN * 16; i += 256) {       // 64 floats/row = 16 float4
            int c = i >> 4, ch = i & 15;
            float4 v = __ldg((const float4*)(xb + (size_t)c * HW) + ch);
            half2 h0 = __floats2half2_rn(v.x, v.y);
            half2 h1 = __floats2half2_rn(v.z, v.w);
            uint2 st;
            st.x = *(uint32_t*)&h0;
            st.y = *(uint32_t*)&h1;
            *(uint2*)&sx[c * SX + 4 * ch] = st;
        }
        asm volatile("cp.async.wait_group 0;");
    }
    __syncthreads();

    const int warp = tid >> 5, lane = tid & 31;
    const int gid = lane >> 2, tig = lane & 3;

    // GEMM1: H = relu(W1 * X + b1);  warp tile 32m x 32p (4 m-warps x 2 n-warps)
    const int m0 = (warp >> 1) * 32;
    const int n0 = (warp & 1) * 32;

    float acc[2][4][4];
    #pragma unroll
    for (int mi = 0; mi < 2; mi++)
        #pragma unroll
        for (int nt = 0; nt < 4; nt++)
            #pragma unroll
            for (int q = 0; q < 4; q++) acc[mi][nt][q] = 0.0f;

    const uint32_t aBase = smem_u32(sw1) + (uint32_t)(((m0 + (lane & 15)) * SW1 + 8 * (lane >> 4)) * 2);
    const uint32_t bBase = smem_u32(sx)  + (uint32_t)(((((lane & 7) + 8 * ((lane >> 3) & 1)) * SX) + n0 + 8 * (lane >> 4)) * 2);

    #pragma unroll
    for (int kt = 0; kt < 16; kt++) {
        const int k0 = kt * 16;
        uint32_t a[2][4];
        ldsm4(a[0], aBase + (uint32_t)(k0 * 2));
        ldsm4(a[1], aBase + (uint32_t)((16 * SW1 + k0) * 2));
        uint32_t bf[4][2];
        #pragma unroll
        for (int nb4 = 0; nb4 < 2; nb4++) {
            uint32_t r0, r1, r2, r3;
            ldsm4t(r0, r1, r2, r3, bBase + (uint32_t)((k0 * SX + 16 * nb4) * 2));
            bf[2 * nb4][0] = r0; bf[2 * nb4][1] = r1;
            bf[2 * nb4 + 1][0] = r2; bf[2 * nb4 + 1][1] = r3;
        }
        #pragma unroll
        for (int mi = 0; mi < 2; mi++)
            #pragma unroll
            for (int nt = 0; nt < 4; nt++)
                mma16816(acc[mi][nt], a[mi], bf[nt][0], bf[nt][1]);
    }
    __syncthreads();

    // epilogue 1: bias + relu -> fp16 H
    #pragma unroll
    for (int mi = 0; mi < 2; mi++) {
        const int r = m0 + 16 * mi + gid;
        const float bb0 = __ldg(b1 + r);
        const float bb1 = __ldg(b1 + r + 8);
        #pragma unroll
        for (int nt = 0; nt < 4; nt++) {
            const int col = n0 + 8 * nt + 2 * tig;
            float v0 = fmaxf(acc[mi][nt][0] + bb0, 0.0f);
            float v1 = fmaxf(acc[mi][nt][1] + bb0, 0.0f);
            float v2 = fmaxf(acc[mi][nt][2] + bb1, 0.0f);
            float v3 = fmaxf(acc[mi][nt][3] + bb1, 0.0f);
            *(half2*)&sH[r * SH + col]       = __floats2half2_rn(v0, v1);
            *(half2*)&sH[(r + 8) * SH + col] = __floats2half2_rn(v2, v3);
        }
    }
    __syncthreads();

    // GEMM2: A = softplus(W2 * H + b2); warps 0-3 each do 16a x 16p
    if (warp < 4) {
        const int n0b = 16 * warp;
        float acc2[2][4] = {{0.f,0.f,0.f,0.f},{0.f,0.f,0.f,0.f}};
        const uint32_t aB2 = smem_u32(sw2) + (uint32_t)((((lane & 15) * SW2) + 8 * (lane >> 4)) * 2);
        const uint32_t bB2 = smem_u32(sH)  + (uint32_t)(((((lane & 7) + 8 * ((lane >> 3) & 1)) * SH) + n0b + 8 * (lane >> 4)) * 2);
        #pragma unroll
        for (int kk = 0; kk < 8; kk++) {
            uint32_t a2r[4];
            ldsm4(a2r, aB2 + (uint32_t)(16 * kk * 2));
            uint32_t r0, r1, r2, r3;
            ldsm4t(r0, r1, r2, r3, bB2 + (uint32_t)(16 * kk * SH * 2));
            mma16816(acc2[0], a2r, r0, r1);
            mma16816(acc2[1], a2r, r2, r3);
        }
        const float bb0 = __ldg(b2 + gid);
        const float bb1 = __ldg(b2 + gid + 8);
        #pragma unroll
        for (int s = 0; s < 2; s++) {
            const int colb = n0b + 8 * s + 2 * tig;
            sA[gid * SAS + colb]           = softplus_f(acc2[s][0] + bb0);
            sA[gid * SAS + colb + 1]       = softplus_f(acc2[s][1] + bb0);
            sA[(gid + 8) * SAS + colb]     = softplus_f(acc2[s][2] + bb1);
            sA[(gid + 8) * SAS + colb + 1] = softplus_f(acc2[s][3] + bb1);
        }
    }
    __syncthreads();

    // write C-scaled A tile coalesced: g_A[n][a][px] = C * A
    {
        float* Ag = g_A + (size_t)n * NATT * HW + p0;
        #pragma unroll
        for (int i = tid; i < NATT * BP; i += 256) {
            int a = i >> 6, p = i & 63;
            Ag[(size_t)a * HW + p] = CSCALE * sA[a * SAS + p];
        }
    }
}

// ---------------- kernel 2: attractor update, f16x2 packed, grid=1024 ----------------
__global__ void __launch_bounds__(256)
zoe_attractor_kernel(const float* __restrict__ b_prev, float* __restrict__ out) {
    const int blk = blockIdx.x;          // 1024 blocks: 128-px tile x 32-bin half
    const int n   = blk >> 8;
    const int t   = (blk >> 1) & 127;    // pixel tile
    const int h   = blk & 1;             // bin half: [32h, 32h+32)
    const int p0  = t * 128;
    const int pr  = threadIdx.x & 63;    // pixel pair within tile
    const int q   = threadIdx.x >> 6;    // 8-bin group within half
    const int px  = p0 + 2 * pr;

    const float2* Ap = (const float2*)(g_A + (size_t)n * NATT * HW + px);
    float a0[NATT], a1[NATT];
    #pragma unroll
    for (int a = 0; a < NATT; a++) {
        float2 v = __ldg(Ap + (size_t)a * (HW / 2));
        a0[a] = v.x; a1[a] = v.y;
    }

    const size_t base = ((size_t)n * NBIN + h * 32 + q * 8) * HW + px;
    const float2* bp = (const float2*)(b_prev + base);
    float2* o1 = (float2*)(out + base);
    float2* o2 = (float2*)(out + base + (size_t)NIMG * NBIN * HW);

    #pragma unroll 2
    for (int j = 0; j < 8; j++) {
        const size_t off = (size_t)j * (HW / 2);
        const float2 b = __ldg(bp + off);
        const float cb0 = CSCALE * b.x;
        const float cb1 = CSCALE * b.y;

        __half2 accA = __floats2half2_rn(0.0f, 0.0f);
        __half2 accB = accA;
        #pragma unroll
        for (int a = 0; a < NATT; a += 2) {
            {
                float u0 = a0[a] - cb0;
                float u1 = a1[a] - cb1;
                __half2 u2 = __floats2half2_rn(u0, u1);
                __half2 y2 = __hneg2(__hmul2(u2, u2));
                uint32_t uy = *(uint32_t*)&y2, ue;
                asm("ex2.approx.f16x2 %0, %1;" : "=r"(ue) : "r"(uy));
                accA = __hfma2(*(__half2*)&ue, u2, accA);
            }
            {
                float u0 = a0[a + 1] - cb0;
                float u1 = a1[a + 1] - cb1;
                __half2 u2 = __floats2half2_rn(u0, u1);
                __half2 y2 = __hneg2(__hmul2(u2, u2));
                uint32_t uy = *(uint32_t*)&y2, ue;
                asm("ex2.approx.f16x2 %0, %1;" : "=r"(ue) : "r"(uy));
                accB = __hfma2(*(__half2*)&ue, u2, accB);
            }
        }
        float s0 = __low2float(accA)  + __low2float(accB);
        float s1 = __high2float(accA) + __high2float(accB);
        float2 dv;
        dv.x = fmaf(s0, INVC, b.x);
        dv.y = fmaf(s1, INVC, b.y);
        o1[off] = dv;
        o2[off] = dv;
    }
}

extern "C" void kernel_launch(void* const* d_in, const int* in_sizes, int n_in,
                              void* d_out, int out_size) {
    const float* x      = (const float*)d_in[0];
    const float* b_prev = (const float*)d_in[1];
    const float* w1     = (const float*)d_in[2];
    const float* b1     = (const float*)d_in[3];
    const float* w2     = (const float*)d_in[4];
    const float* b2     = (const float*)d_in[5];
    float* out = (float*)d_out;

    convert_weights<<<(NW1 + NW2 + 255) / 256, 256>>>(w1, w2);

    cudaFuncSetAttribute(zoe_mlp_kernel,
                         cudaFuncAttributeMaxDynamicSharedMemorySize, SMEM_TOTAL);
    zoe_mlp_kernel<<<NIMG * (HW / BP), 256, SMEM_TOTAL>>>(x, b1, b2);

    zoe_attractor_kernel<<<NIMG * 256, 256>>>(b_prev, out);
}

// round 13
// speedup vs baseline: 1.1912x; 1.1912x over previous
#include <cuda_runtime.h>
#include <cuda_fp16.h>
#include <cstdint>

#define NIMG 4
#define CIN  256
#define HW   16384
#define MLP  128
#define NATT 16
#define NBIN 64
#define BP   64      // pixels per block (MLP kernel)

#define SX   72      // halves stride, x tile [CIN][BP]    (36 words % 32 == 4 -> conflict-free)
#define SW1  264     // halves stride, w1 [MLP][CIN]
#define SW2  136     // halves stride, w2 [NATT][MLP]
#define SH   72      // halves stride, H tile (aliases x region)
#define SAS  68      // floats stride, A tile (aliases w1 region)

#define OFF_X   0
#define OFF_W1  (CIN * SX * 2)               // 36864
#define OFF_W2  (OFF_W1 + MLP * SW1 * 2)     // 104448
#define SMEM_TOTAL (OFF_W2 + NATT * SW2 * 2) // 108800 -> 2 CTAs/SM

// C = sqrt(300 * log2(e)); exp(-300 dx^2) = 2^(-(C*dx)^2)
#define CSCALE 20.80405045f
#define INVC   0.048067556f

// device-global scratch (no runtime allocation allowed)
__device__ __half g_xh[NIMG * CIN * HW];    // 33.5 MB fp16 x
__device__ __half g_w1h[MLP * CIN];
__device__ __half g_w2h[NATT * MLP];
__device__ float  g_A[NIMG * NATT * HW];    // 4 MB, C-scaled A

#define NX4   (NIMG * CIN * HW / 4)         // 4194304 float4 of x
#define NX4Q  (NX4 / 4)                     // 1048576 (4 float4 per thread)
#define NW1   (MLP * CIN / 2)               // 16384 half2
#define NW2   (NATT * MLP / 2)              // 1024 half2

// ---------------- kernel 0: fp32 -> fp16 conversion (streaming, 4x ILP) ----------------
__global__ void __launch_bounds__(256)
convert_inputs(const float* __restrict__ x,
               const float* __restrict__ w1,
               const float* __restrict__ w2) {
    int i = blockIdx.x * blockDim.x + threadIdx.x;
    if (i < NX4Q) {
        float4 v0 = __ldg((const float4*)x + i);
        float4 v1 = __ldg((const float4*)x + i + NX4Q);
        float4 v2 = __ldg((const float4*)x + i + 2 * NX4Q);
        float4 v3 = __ldg((const float4*)x + i + 3 * NX4Q);
        uint2 s0, s1, s2, s3;
        half2 h;
        h = __floats2half2_rn(v0.x, v0.y); s0.x = *(uint32_t*)&h;
        h = __floats2half2_rn(v0.z, v0.w); s0.y = *(uint32_t*)&h;
        h = __floats2half2_rn(v1.x, v1.y); s1.x = *(uint32_t*)&h;
        h = __floats2half2_rn(v1.z, v1.w); s1.y = *(uint32_t*)&h;
        h = __floats2half2_rn(v2.x, v2.y); s2.x = *(uint32_t*)&h;
        h = __floats2half2_rn(v2.z, v2.w); s2.y = *(uint32_t*)&h;
        h = __floats2half2_rn(v3.x, v3.y); s3.x = *(uint32_t*)&h;
        h = __floats2half2_rn(v3.z, v3.w); s3.y = *(uint32_t*)&h;
        *(uint2*)&g_xh[4 * i]              = s0;
        *(uint2*)&g_xh[4 * (i + NX4Q)]     = s1;
        *(uint2*)&g_xh[4 * (i + 2 * NX4Q)] = s2;
        *(uint2*)&g_xh[4 * (i + 3 * NX4Q)] = s3;
    } else {
        int j = i - NX4Q;
        if (j < NW1) {
            float2 v = __ldg((const float2*)w1 + j);
            *(half2*)&g_w1h[2 * j] = __floats2half2_rn(v.x, v.y);
        } else if (j < NW1 + NW2) {
            int k = j - NW1;
            float2 v = __ldg((const float2*)w2 + k);
            *(half2*)&g_w2h[2 * k] = __floats2half2_rn(v.x, v.y);
        }
    }
}

__device__ __forceinline__ uint32_t smem_u32(const void* p) {
    return (uint32_t)__cvta_generic_to_shared(p);
}
__device__ __forceinline__ void cpa16(uint32_t dst, const void* src) {
    asm volatile("cp.async.ca.shared.global [%0], [%1], 16;" :: "r"(dst), "l"(src));
}
__device__ __forceinline__ void ldsm4(uint32_t* r, uint32_t a) {
    asm volatile("ldmatrix.sync.aligned.m8n8.x4.shared.b16 {%0,%1,%2,%3}, [%4];"
                 : "=r"(r[0]), "=r"(r[1]), "=r"(r[2]), "=r"(r[3]) : "r"(a));
}
__device__ __forceinline__ void ldsm4t(uint32_t& r0, uint32_t& r1, uint32_t& r2, uint32_t& r3, uint32_t a) {
    asm volatile("ldmatrix.sync.aligned.m8n8.x4.trans.shared.b16 {%0,%1,%2,%3}, [%4];"
                 : "=r"(r0), "=r"(r1), "=r"(r2), "=r"(r3) : "r"(a));
}
__device__ __forceinline__ void mma16816(float* c, const uint32_t* a, uint32_t b0, uint32_t b1) {
    asm volatile("mma.sync.aligned.m16n8k16.row.col.f32.f16.f16.f32 "
                 "{%0,%1,%2,%3}, {%4,%5,%6,%7}, {%8,%9}, {%0,%1,%2,%3};"
                 : "+f"(c[0]), "+f"(c[1]), "+f"(c[2]), "+f"(c[3])
                 : "r"(a[0]), "r"(a[1]), "r"(a[2]), "r"(a[3]), "r"(b0), "r"(b1));
}
__device__ __forceinline__ float softplus_f(float v) {
    return fmaxf(v, 0.0f) + log1pf(__expf(-fabsf(v)));
}

// ---------------- kernel 1: fused 1x1-conv MLP head -> scaled A scratch ----------------
// BP=64 pixels per CTA, 108.8KB smem -> 2 CTAs/SM; all staging via cp.async.
__global__ void __launch_bounds__(256, 2)
zoe_mlp_kernel(const float* __restrict__ b1,
               const float* __restrict__ b2) {
    extern __shared__ char smem[];
    __half* sx  = (__half*)(smem + OFF_X);
    __half* sw1 = (__half*)(smem + OFF_W1);
    __half* sw2 = (__half*)(smem + OFF_W2);
    __half* sH  = sx;                       // H tile [128][SH] aliases x region
    float*  sA  = (float*)(smem + OFF_W1);  // A tile [16][SAS] aliases w1 region

    const int tid = threadIdx.x;
    const int blk = blockIdx.x;             // 0..1023
    const int n   = blk >> 8;               // image
    const int p0  = (blk & 255) * BP;       // pixel tile start

    // ---- stage x / w1 / w2 with cp.async (fire-and-forget, 16B chunks) ----
    {
        const uint32_t sxb = smem_u32(sx);
        const __half* xb = g_xh + (size_t)n * CIN * HW + p0;
        #pragma unroll 4
        for (int i = tid; i < CIN * 8; i += 256) {        // 64 halves/row = 8 chunks
            int c = i >> 3, ch = i & 7;
            cpa16(sxb + (uint32_t)(c * (SX * 2) + ch * 16), xb + (size_t)c * HW + ch * 8);
        }
        const uint32_t sw1b = smem_u32(sw1);
        #pragma unroll 4
        for (int i = tid; i < MLP * 32; i += 256) {       // 256 halves/row = 32 chunks
            int m = i >> 5, ch = i & 31;
            cpa16(sw1b + (uint32_t)(m * (SW1 * 2) + ch * 16), g_w1h + m * CIN + ch * 8);
        }
        const uint32_t sw2b = smem_u32(sw2);
        for (int i = tid; i < NATT * 16; i += 256) {      // 128 halves/row = 16 chunks
            int m = i >> 4, ch = i & 15;
            cpa16(sw2b + (uint32_t)(m * (SW2 * 2) + ch * 16), g_w2h + m * MLP + ch * 8);
        }
        asm volatile("cp.async.commit_group;");
        asm volatile("cp.async.wait_group 0;");
    }
    __syncthreads();

    const int warp = tid >> 5, lane = tid & 31;
    const int gid = lane >> 2, tig = lane & 3;

    // GEMM1: H = relu(W1 * X + b1);  warp tile 32m x 32p (4 m-warps x 2 n-warps)
    const int m0 = (warp >> 1) * 32;
    const int n0 = (warp & 1) * 32;

    float acc[2][4][4];
    #pragma unroll
    for (int mi = 0; mi < 2; mi++)
        #pragma unroll
        for (int nt = 0; nt < 4; nt++)
            #pragma unroll
            for (int q = 0; q < 4; q++) acc[mi][nt][q] = 0.0f;

    const uint32_t aBase = smem_u32(sw1) + (uint32_t)(((m0 + (lane & 15)) * SW1 + 8 * (lane >> 4)) * 2);
    const uint32_t bBase = smem_u32(sx)  + (uint32_t)(((((lane & 7) + 8 * ((lane >> 3) & 1)) * SX) + n0 + 8 * (lane >> 4)) * 2);

    #pragma unroll
    for (int kt = 0; kt < 16; kt++) {
        const int k0 = kt * 16;
        uint32_t a[2][4];
        ldsm4(a[0], aBase + (uint32_t)(k0 * 2));
        ldsm4(a[1], aBase + (uint32_t)((16 * SW1 + k0) * 2));
        uint32_t bf[4][2];
        #pragma unroll
        for (int nb4 = 0; nb4 < 2; nb4++) {
            uint32_t r0, r1, r2, r3;
            ldsm4t(r0, r1, r2, r3, bBase + (uint32_t)((k0 * SX + 16 * nb4) * 2));
            bf[2 * nb4][0] = r0; bf[2 * nb4][1] = r1;
            bf[2 * nb4 + 1][0] = r2; bf[2 * nb4 + 1][1] = r3;
        }
        #pragma unroll
        for (int mi = 0; mi < 2; mi++)
            #pragma unroll
            for (int nt = 0; nt < 4; nt++)
                mma16816(acc[mi][nt], a[mi], bf[nt][0], bf[nt][1]);
    }
    __syncthreads();

    // epilogue 1: bias + relu -> fp16 H
    #pragma unroll
    for (int mi = 0; mi < 2; mi++) {
        const int r = m0 + 16 * mi + gid;
        const float bb0 = __ldg(b1 + r);
        const float bb1 = __ldg(b1 + r + 8);
        #pragma unroll
        for (int nt = 0; nt < 4; nt++) {
            const int col = n0 + 8 * nt + 2 * tig;
            float v0 = fmaxf(acc[mi][nt][0] + bb0, 0.0f);
            float v1 = fmaxf(acc[mi][nt][1] + bb0, 0.0f);
            float v2 = fmaxf(acc[mi][nt][2] + bb1, 0.0f);
            float v3 = fmaxf(acc[mi][nt][3] + bb1, 0.0f);
            *(half2*)&sH[r * SH + col]       = __floats2half2_rn(v0, v1);
            *(half2*)&sH[(r + 8) * SH + col] = __floats2half2_rn(v2, v3);
        }
    }
    __syncthreads();

    // GEMM2: A = softplus(W2 * H + b2); warps 0-3 each do 16a x 16p
    if (warp < 4) {
        const int n0b = 16 * warp;
        float acc2[2][4] = {{0.f,0.f,0.f,0.f},{0.f,0.f,0.f,0.f}};
        const uint32_t aB2 = smem_u32(sw2) + (uint32_t)((((lane & 15) * SW2) + 8 * (lane >> 4)) * 2);
        const uint32_t bB2 = smem_u32(sH)  + (uint32_t)(((((lane & 7) + 8 * ((lane >> 3) & 1)) * SH) + n0b + 8 * (lane >> 4)) * 2);
        #pragma unroll
        for (int kk = 0; kk < 8; kk++) {
            uint32_t a2r[4];
            ldsm4(a2r, aB2 + (uint32_t)(16 * kk * 2));
            uint32_t r0, r1, r2, r3;
            ldsm4t(r0, r1, r2, r3, bB2 + (uint32_t)(16 * kk * SH * 2));
            mma16816(acc2[0], a2r, r0, r1);
            mma16816(acc2[1], a2r, r2, r3);
        }
        const float bb0 = __ldg(b2 + gid);
        const float bb1 = __ldg(b2 + gid + 8);
        #pragma unroll
        for (int s = 0; s < 2; s++) {
            const int colb = n0b + 8 * s + 2 * tig;
            sA[gid * SAS + colb]           = softplus_f(acc2[s][0] + bb0);
            sA[gid * SAS + colb + 1]       = softplus_f(acc2[s][1] + bb0);
            sA[(gid + 8) * SAS + colb]     = softplus_f(acc2[s][2] + bb1);
            sA[(gid + 8) * SAS + colb + 1] = softplus_f(acc2[s][3] + bb1);
        }
    }
    __syncthreads();

    // write C-scaled A tile coalesced: g_A[n][a][px] = C * A
    {
        float* Ag = g_A + (size_t)n * NATT * HW + p0;
        #pragma unroll
        for (int i = tid; i < NATT * BP; i += 256) {
            int a = i >> 6, p = i & 63;
            Ag[(size_t)a * HW + p] = CSCALE * sA[a * SAS + p];
        }
    }
}

// ---------------- kernel 2: attractor update, f16x2 packed, grid=1024 ----------------
__global__ void __launch_bounds__(256)
zoe_attractor_kernel(const float* __restrict__ b_prev, float* __restrict__ out) {
    const int blk = blockIdx.x;          // 1024 blocks: 128-px tile x 32-bin half
    const int n   = blk >> 8;
    const int t   = (blk >> 1) & 127;    // pixel tile
    const int h   = blk & 1;             // bin half: [32h, 32h+32)
    const int p0  = t * 128;
    const int pr  = threadIdx.x & 63;    // pixel pair within tile
    const int q   = threadIdx.x >> 6;    // 8-bin group within half
    const int px  = p0 + 2 * pr;

    const float2* Ap = (const float2*)(g_A + (size_t)n * NATT * HW + px);
    float a0[NATT], a1[NATT];
    #pragma unroll
    for (int a = 0; a < NATT; a++) {
        float2 v = __ldg(Ap + (size_t)a * (HW / 2));
        a0[a] = v.x; a1[a] = v.y;
    }

    const size_t base = ((size_t)n * NBIN + h * 32 + q * 8) * HW + px;
    const float2* bp = (const float2*)(b_prev + base);
    float2* o1 = (float2*)(out + base);
    float2* o2 = (float2*)(out + base + (size_t)NIMG * NBIN * HW);

    #pragma unroll 2
    for (int j = 0; j < 8; j++) {
        const size_t off = (size_t)j * (HW / 2);
        const float2 b = __ldg(bp + off);
        const float cb0 = CSCALE * b.x;
        const float cb1 = CSCALE * b.y;

        __half2 accA = __floats2half2_rn(0.0f, 0.0f);
        __half2 accB = accA;
        #pragma unroll
        for (int a = 0; a < NATT; a += 2) {
            {
                float u0 = a0[a] - cb0;
                float u1 = a1[a] - cb1;
                __half2 u2 = __floats2half2_rn(u0, u1);
                __half2 y2 = __hneg2(__hmul2(u2, u2));
                uint32_t uy = *(uint32_t*)&y2, ue;
                asm("ex2.approx.f16x2 %0, %1;" : "=r"(ue) : "r"(uy));
                accA = __hfma2(*(__half2*)&ue, u2, accA);
            }
            {
                float u0 = a0[a + 1] - cb0;
                float u1 = a1[a + 1] - cb1;
                __half2 u2 = __floats2half2_rn(u0, u1);
                __half2 y2 = __hneg2(__hmul2(u2, u2));
                uint32_t uy = *(uint32_t*)&y2, ue;
                asm("ex2.approx.f16x2 %0, %1;" : "=r"(ue) : "r"(uy));
                accB = __hfma2(*(__half2*)&ue, u2, accB);
            }
        }
        float s0 = __low2float(accA)  + __low2float(accB);
        float s1 = __high2float(accA) + __high2float(accB);
        float2 dv;
        dv.x = fmaf(s0, INVC, b.x);
        dv.y = fmaf(s1, INVC, b.y);
        o1[off] = dv;
        o2[off] = dv;
    }
}

extern "C" void kernel_launch(void* const* d_in, const int* in_sizes, int n_in,
                              void* d_out, int out_size) {
    const float* x      = (const float*)d_in[0];
    const float* b_prev = (const float*)d_in[1];
    const float* w1     = (const float*)d_in[2];
    const float* b1     = (const float*)d_in[3];
    const float* w2     = (const float*)d_in[4];
    const float* b2     = (const float*)d_in[5];
    float* out = (float*)d_out;

    const int ntot = NX4Q + NW1 + NW2;
    convert_inputs<<<(ntot + 255) / 256, 256>>>(x, w1, w2);

    cudaFuncSetAttribute(zoe_mlp_kernel,
                         cudaFuncAttributeMaxDynamicSharedMemorySize, SMEM_TOTAL);
    zoe_mlp_kernel<<<NIMG * (HW / BP), 256, SMEM_TOTAL>>>(b1, b2);

    zoe_attractor_kernel<<<NIMG * 256, 256>>>(b_prev, out);
}